// round 3
// baseline (speedup 1.0000x reference)
#include <cuda_runtime.h>

// Problem constants
#define B_TOTAL  2
#define C_IN     32
#define HDIM     64
#define WDIM     64
#define J_TOTAL  4096
#define S_TOTAL  256
#define HID      64
#define C_OUT    32
#define JPB      16
#define SCHUNK   128

typedef unsigned long long ull;

// Scratch
__device__ float g_Q[B_TOTAL * S_TOTAL * HID];
__device__ float g_SQ[B_TOTAL * HID];          // sum_s Q[b,s,h]

// ---------- packed f32x2 helpers (sm_100a) ----------
__device__ __forceinline__ ull f2x2(float lo, float hi) {
    ull r; asm("mov.b64 %0, {%1,%2};" : "=l"(r) : "f"(lo), "f"(hi)); return r;
}
__device__ __forceinline__ void unpk(ull v, float& lo, float& hi) {
    asm("mov.b64 {%0,%1}, %2;" : "=f"(lo), "=f"(hi) : "l"(v));
}
__device__ __forceinline__ ull fma2(ull a, ull b, ull c) {
    ull d; asm("fma.rn.f32x2 %0, %1, %2, %3;" : "=l"(d) : "l"(a), "l"(b), "l"(c)); return d;
}
__device__ __forceinline__ ull mul2(ull a, ull b) {
    ull d; asm("mul.rn.f32x2 %0, %1, %2;" : "=l"(d) : "l"(a), "l"(b)); return d;
}
__device__ __forceinline__ ull add2(ull a, ull b) {
    ull d; asm("add.rn.f32x2 %0, %1, %2;" : "=l"(d) : "l"(a), "l"(b)); return d;
}
__device__ __forceinline__ float rcpf(float x) {
    float r; asm("rcp.approx.f32 %0, %1;" : "=f"(r) : "f"(x)); return r;
}
__device__ __forceinline__ float ex2f(float x) {
    float r; asm("ex2.approx.f32 %0, %1;" : "=f"(r) : "f"(x)); return r;
}
__device__ __forceinline__ ull dup(float f) {
    unsigned u = __float_as_uint(f); return ((ull)u << 32) | (ull)u;
}

// ---------- kernel 1: Q[b,s,h] ----------
__global__ void precompute_q(const float* __restrict__ v,
                             const int* __restrict__ indices,
                             const float* __restrict__ W1,
                             const float* __restrict__ b1) {
    int s = blockIdx.x;
    int b = blockIdx.y;
    int h = threadIdx.x;
    int idx = indices[s] & (J_TOTAL - 1);
    int ix = idx & (WDIM - 1);
    int iy = idx >> 6;
    float sx = ix * (1.0f / 63.0f);
    float sy = iy * (1.0f / 63.0f);
    float acc = b1[h] - sx * W1[h] - sy * W1[HID + h];
    const float* vb = v + (size_t)b * C_IN * J_TOTAL + idx;
#pragma unroll
    for (int c = 0; c < C_IN; c++)
        acc = fmaf(vb[(size_t)c * J_TOTAL], W1[(2 + c) * HID + h], acc);
    g_Q[(b * S_TOTAL + s) * HID + h] = acc;
}

// ---------- kernel 2: SQ[b,h] = sum_s Q ----------
__global__ void precompute_sq() {
    int h = threadIdx.x;
    int b = blockIdx.x;
    float acc = 0.0f;
    const float* Qb = g_Q + (size_t)b * S_TOTAL * HID;
#pragma unroll 8
    for (int s = 0; s < S_TOTAL; s++) acc += Qb[s * HID + h];
    g_SQ[b * HID + h] = acc;
}

// ---------- kernel 3: main ----------
__global__ __launch_bounds__(256)
void nystrom_main(const float* __restrict__ W1,
                  const float* __restrict__ W2,
                  const float* __restrict__ b2,
                  float* __restrict__ out) {
    __shared__ float Qs[SCHUNK * HID];     // 32 KB; reused as Gs in epilogue
    __shared__ float W2s[HID * C_OUT];
    __shared__ float w1x[HID];
    __shared__ float w1y[HID];
    __shared__ float b2s[C_OUT];

    int tid   = threadIdx.x;
    int b     = blockIdx.y;
    int j0    = blockIdx.x * JPB;
    int group = tid >> 6;
    int h     = tid & 63;

    if (tid < HID) { w1x[tid] = W1[tid]; w1y[tid] = W1[HID + tid]; }
    if (tid >= 64 && tid < 64 + C_OUT) b2s[tid - 64] = b2[tid - 64];
    for (int i = tid; i < HID * C_OUT; i += 256) W2s[i] = W2[i];
    __syncthreads();

    // Per-thread: 4 j's as 2 packed chains
    float a[4];
#pragma unroll
    for (int i = 0; i < 4; i++) {
        int j = j0 + group * 4 + i;
        float x = (j & (WDIM - 1)) * (1.0f / 63.0f);
        float y = (j >> 6)         * (1.0f / 63.0f);
        a[i] = fmaf(x, w1x[h], y * w1y[h]);
    }
    ull a2[2] = { f2x2(a[0], a[1]), f2x2(a[2], a[3]) };
    ull acc2[2] = { 0ull, 0ull };

    // Packed constants (A-S 7.1.26 erf)
    const ull kIS2  = dup(0.70710678118654752f);
    const ull kP    = dup(0.3275911f);
    const ull kONE  = dup(1.0f);
    const ull kA1   = dup(0.254829592f);
    const ull kA2   = dup(-0.284496736f);
    const ull kA3   = dup(1.421413741f);
    const ull kA4   = dup(-1.453152027f);
    const ull kA5   = dup(1.061405429f);
    const ull kNL2E = dup(-1.44269504088896f);
    const ull kNEG1 = dup(-1.0f);
    const ull kHALF = dup(0.5f);
    const ull ABSM  = 0x7FFFFFFF7FFFFFFFULL;
    const ull SGNM  = 0x8000000080000000ULL;

    const float* Qg = g_Q + (size_t)b * S_TOTAL * HID;
#pragma unroll
    for (int chunk = 0; chunk < 2; chunk++) {
        __syncthreads();
        for (int i = tid; i < SCHUNK * HID; i += 256)
            Qs[i] = Qg[chunk * SCHUNK * HID + i];
        __syncthreads();
#pragma unroll 4
        for (int s = 0; s < SCHUNK; s++) {
            float q = Qs[s * HID + h];
            ull q2 = f2x2(q, q);
#pragma unroll
            for (int pp = 0; pp < 2; pp++) {
                ull t2  = add2(a2[pp], q2);
                ull u2  = mul2(t2, kIS2);
                ull au2 = u2 & ABSM;
                ull d2  = fma2(au2, kP, kONE);
                float dl, dh; unpk(d2, dl, dh);
                ull k2  = f2x2(rcpf(dl), rcpf(dh));
                ull p2  = fma2(k2, kA5, kA4);
                p2 = fma2(p2, k2, kA3);
                p2 = fma2(p2, k2, kA2);
                p2 = fma2(p2, k2, kA1);
                p2 = mul2(p2, k2);
                ull z2 = mul2(u2, kNL2E);
                ull y2 = mul2(z2, u2);
                float yl, yh; unpk(y2, yl, yh);
                ull e2  = f2x2(ex2f(yl), ex2f(yh));
                ull pe2 = mul2(p2, e2);
                ull om2 = fma2(pe2, kNEG1, kONE);       // 1 - pe  (>= -1ulp)
                ull cs2 = om2 | (u2 & SGNM);            // copysign(1-pe, u)
                ull ht2 = mul2(t2, kHALF);
                acc2[pp] = fma2(ht2, cs2, acc2[pp]);    // sum of ht*cs; +ht added analytically
            }
        }
    }

    // full sum_s gelu = acc + 0.5*(S*a + SQ[h])
    float sq = g_SQ[b * HID + h];
    float sums[4];
    unpk(acc2[0], sums[0], sums[1]);
    unpk(acc2[1], sums[2], sums[3]);
#pragma unroll
    for (int i = 0; i < 4; i++)
        sums[i] += 0.5f * fmaf((float)S_TOTAL, a[i], sq);

    // Epilogue
    __syncthreads();
    float* Gs = Qs;
#pragma unroll
    for (int i = 0; i < 4; i++)
        Gs[(group * 4 + i) * HID + h] = sums[i];
    __syncthreads();

#pragma unroll
    for (int r = 0; r < 2; r++) {
        int idx = tid + r * 256;
        int jj  = idx >> 5;
        int c   = idx & 31;
        float sum = 0.0f;
#pragma unroll
        for (int hh = 0; hh < HID; hh++)
            sum = fmaf(Gs[jj * HID + hh], W2s[hh * C_OUT + c], sum);
        out[((size_t)b * C_OUT + c) * J_TOTAL + (j0 + jj)] =
            fmaf(sum, 1.0f / (float)S_TOTAL, b2s[c]);
    }
}

extern "C" void kernel_launch(void* const* d_in, const int* in_sizes, int n_in,
                              void* d_out, int out_size) {
    const float* v       = (const float*)d_in[0];
    const int*   indices = (const int*)d_in[1];
    const float* W1      = (const float*)d_in[2];
    const float* b1      = (const float*)d_in[3];
    const float* W2      = (const float*)d_in[4];
    const float* b2      = (const float*)d_in[5];
    float*       out     = (float*)d_out;

    precompute_q<<<dim3(S_TOTAL, B_TOTAL), HID>>>(v, indices, W1, b1);
    precompute_sq<<<B_TOTAL, HID>>>();
    nystrom_main<<<dim3(J_TOTAL / JPB, B_TOTAL), 256>>>(W1, W2, b2, out);
}

// round 4
// speedup vs baseline: 1.5499x; 1.5499x over previous
#include <cuda_runtime.h>

// Problem constants
#define B_TOTAL  2
#define C_IN     32
#define HDIM     64
#define WDIM     64
#define J_TOTAL  4096
#define S_TOTAL  256
#define HID      64
#define C_OUT    32
#define JPB      8       // j tiles per block (1024 blocks -> ~7/SM, single balanced wave)
#define SCHUNK   64      // s-chunk staged in smem (16KB)

// Scratch: Q[b,s,h] = b1[h] - sx*W1[0,h] - sy*W1[1,h] + sum_c v[b,c,idx_s]*W1[2+c,h]
__device__ float g_Q[B_TOTAL * S_TOTAL * HID];

__device__ __forceinline__ float rcpf(float x) {
    float r; asm("rcp.approx.f32 %0, %1;" : "=f"(r) : "f"(x)); return r;
}
__device__ __forceinline__ float ex2f(float x) {
    float r; asm("ex2.approx.f32 %0, %1;" : "=f"(r) : "f"(x)); return r;
}

// ---------- kernel 1: Q[b,s,h] ----------
__global__ void precompute_q(const float* __restrict__ v,
                             const int* __restrict__ indices,
                             const float* __restrict__ W1,
                             const float* __restrict__ b1) {
    int s = blockIdx.x;
    int b = blockIdx.y;
    int h = threadIdx.x;
    int idx = indices[s] & (J_TOTAL - 1);
    int ix = idx & (WDIM - 1);
    int iy = idx >> 6;
    float sx = ix * (1.0f / 63.0f);
    float sy = iy * (1.0f / 63.0f);
    float acc = b1[h] - sx * W1[h] - sy * W1[HID + h];
    const float* vb = v + (size_t)b * C_IN * J_TOTAL + idx;
#pragma unroll
    for (int c = 0; c < C_IN; c++)
        acc = fmaf(vb[(size_t)c * J_TOTAL], W1[(2 + c) * HID + h], acc);
    g_Q[(b * S_TOTAL + s) * HID + h] = acc;
}

// ---------- kernel 2: main ----------
// gelu_tanh(t) = t * r,  r = 1/(1 + exp2(w)),  w = c1*t + c2*t^3
// c1 = -2*log2(e)*sqrt(2/pi), c2 = c1*0.044715
// t >> 0: w -> -inf, e -> 0, r -> 1, gelu -> t.   t << 0: e -> inf, r -> 0, gelu -> 0.
__global__ __launch_bounds__(256)
void nystrom_main(const float* __restrict__ W1,
                  const float* __restrict__ W2,
                  const float* __restrict__ b2,
                  float* __restrict__ out) {
    __shared__ float Qs[SCHUNK * HID];     // 16 KB; reused as Gs in epilogue
    __shared__ float W2s[HID * C_OUT];     // 8 KB
    __shared__ float w1x[HID];
    __shared__ float w1y[HID];
    __shared__ float b2s[C_OUT];

    const float C1 = -2.302212898f;        // -2*log2e*sqrt(2/pi)
    const float C2 = -0.102948446f;        // C1*0.044715

    int tid   = threadIdx.x;
    int b     = blockIdx.y;
    int j0    = blockIdx.x * JPB;
    int group = tid >> 6;                  // 0..3
    int h     = tid & 63;

    if (tid < HID) { w1x[tid] = W1[tid]; w1y[tid] = W1[HID + tid]; }
    if (tid >= 64 && tid < 64 + C_OUT) b2s[tid - 64] = b2[tid - 64];
    for (int i = tid; i < HID * C_OUT; i += 256) W2s[i] = W2[i];
    __syncthreads();

    // Each thread owns 2 j's (same h): j = j0 + group*2 + i
    float a[2], acc[2];
#pragma unroll
    for (int i = 0; i < 2; i++) {
        int j = j0 + group * 2 + i;
        float x = (j & (WDIM - 1)) * (1.0f / 63.0f);
        float y = (j >> 6)         * (1.0f / 63.0f);
        a[i] = fmaf(x, w1x[h], y * w1y[h]);
        acc[i] = 0.0f;
    }

    const float* Qg = g_Q + (size_t)b * S_TOTAL * HID;
#pragma unroll
    for (int chunk = 0; chunk < S_TOTAL / SCHUNK; chunk++) {
        __syncthreads();  // protect Qs overwrite
        for (int i = tid; i < SCHUNK * HID; i += 256)
            Qs[i] = Qg[chunk * SCHUNK * HID + i];
        __syncthreads();
#pragma unroll 4
        for (int s = 0; s < SCHUNK; s++) {
            float q = Qs[s * HID + h];
#pragma unroll
            for (int i = 0; i < 2; i++) {
                float t  = a[i] + q;
                float t2 = t * t;
                float w  = t * fmaf(C2, t2, C1);
                float e  = ex2f(w);                 // MUFU.EX2
                float r  = rcpf(1.0f + e);          // MUFU.RCP
                acc[i]   = fmaf(t, r, acc[i]);
            }
        }
    }

    // Epilogue: Gs[jj][h] = sum_s gelu; then out[b,c,j] = Gs[j].W2[:,c]/S + b2[c]
    __syncthreads();
    float* Gs = Qs;                        // overlay (8*64 floats)
#pragma unroll
    for (int i = 0; i < 2; i++)
        Gs[(group * 2 + i) * HID + h] = acc[i];
    __syncthreads();

    // 256 outputs = 8 j * 32 c, one per thread
    {
        int jj = tid >> 5;
        int c  = tid & 31;
        float sum = 0.0f;
#pragma unroll
        for (int hh = 0; hh < HID; hh++)
            sum = fmaf(Gs[jj * HID + hh], W2s[hh * C_OUT + c], sum);
        out[((size_t)b * C_OUT + c) * J_TOTAL + (j0 + jj)] =
            fmaf(sum, 1.0f / (float)S_TOTAL, b2s[c]);
    }
}

extern "C" void kernel_launch(void* const* d_in, const int* in_sizes, int n_in,
                              void* d_out, int out_size) {
    const float* v       = (const float*)d_in[0];
    const int*   indices = (const int*)d_in[1];
    const float* W1      = (const float*)d_in[2];
    const float* b1      = (const float*)d_in[3];
    const float* W2      = (const float*)d_in[4];
    const float* b2      = (const float*)d_in[5];
    float*       out     = (float*)d_out;

    precompute_q<<<dim3(S_TOTAL, B_TOTAL), HID>>>(v, indices, W1, b1);
    nystrom_main<<<dim3(J_TOTAL / JPB, B_TOTAL), 256>>>(W1, W2, b2, out);
}

// round 5
// speedup vs baseline: 2.5763x; 1.6623x over previous
#include <cuda_runtime.h>

// Problem constants
#define B_TOTAL  2
#define C_IN     32
#define HDIM     64
#define WDIM     64
#define J_TOTAL  4096
#define S_TOTAL  256
#define HID      64
#define C_OUT    32
#define JPB      8       // 1024 blocks -> ~7/SM, single balanced wave
#define SCHUNK   64      // s-chunk staged in smem (16KB)

// Scratch: Q[b,s,h] = b1[h] - sx*W1[0,h] - sy*W1[1,h] + sum_c v[b,c,idx_s]*W1[2+c,h]
__device__ float g_Q[B_TOTAL * S_TOTAL * HID];

__device__ __forceinline__ float tanhf_hw(float x) {
    float r; asm("tanh.approx.f32 %0, %1;" : "=f"(r) : "f"(x)); return r;
}

// ---------- kernel 1: Q[b,s,h] ----------
__global__ void precompute_q(const float* __restrict__ v,
                             const int* __restrict__ indices,
                             const float* __restrict__ W1,
                             const float* __restrict__ b1) {
    int s = blockIdx.x;
    int b = blockIdx.y;
    int h = threadIdx.x;
    int idx = indices[s] & (J_TOTAL - 1);
    int ix = idx & (WDIM - 1);
    int iy = idx >> 6;
    float sx = ix * (1.0f / 63.0f);
    float sy = iy * (1.0f / 63.0f);
    float acc = b1[h] - sx * W1[h] - sy * W1[HID + h];
    const float* vb = v + (size_t)b * C_IN * J_TOTAL + idx;
#pragma unroll
    for (int c = 0; c < C_IN; c++)
        acc = fmaf(vb[(size_t)c * J_TOTAL], W1[(2 + c) * HID + h], acc);
    g_Q[(b * S_TOTAL + s) * HID + h] = acc;
}

// ---------- kernel 2: main ----------
// gelu_tanh(t) = 0.5*t*(1+tanh(v)), v = sqrt(2/pi)*(t + 0.044715 t^3)
// Loop accumulates acc = sum t*tanh(v) and sq = sum q;
// sum_s gelu = 0.5*(acc + S*a + sq).
__global__ __launch_bounds__(256)
void nystrom_main(const float* __restrict__ W1,
                  const float* __restrict__ W2,
                  const float* __restrict__ b2,
                  float* __restrict__ out) {
    __shared__ float Qs[SCHUNK * HID];     // 16 KB; reused as Gs in epilogue
    __shared__ float W2s[HID * C_OUT];     // 8 KB
    __shared__ float w1x[HID];
    __shared__ float w1y[HID];
    __shared__ float b2s[C_OUT];

    const float C1 = 0.7978845608028654f;  // sqrt(2/pi)
    const float C2 = 0.0356774081f;        // C1*0.044715

    int tid   = threadIdx.x;
    int b     = blockIdx.y;
    int j0    = blockIdx.x * JPB;
    int group = tid >> 6;                  // 0..3
    int h     = tid & 63;

    if (tid < HID) { w1x[tid] = W1[tid]; w1y[tid] = W1[HID + tid]; }
    if (tid >= 64 && tid < 64 + C_OUT) b2s[tid - 64] = b2[tid - 64];
    for (int i = tid; i < HID * C_OUT; i += 256) W2s[i] = W2[i];
    __syncthreads();

    // Each thread owns 2 j's (same h)
    float a[2], acc[2];
#pragma unroll
    for (int i = 0; i < 2; i++) {
        int j = j0 + group * 2 + i;
        float x = (j & (WDIM - 1)) * (1.0f / 63.0f);
        float y = (j >> 6)         * (1.0f / 63.0f);
        a[i] = fmaf(x, w1x[h], y * w1y[h]);
        acc[i] = 0.0f;
    }
    float sq = 0.0f;

    const float* Qg = g_Q + (size_t)b * S_TOTAL * HID;
#pragma unroll
    for (int chunk = 0; chunk < S_TOTAL / SCHUNK; chunk++) {
        __syncthreads();  // protect Qs overwrite
        for (int i = tid; i < SCHUNK * HID; i += 256)
            Qs[i] = Qg[chunk * SCHUNK * HID + i];
        __syncthreads();
#pragma unroll 4
        for (int s = 0; s < SCHUNK; s++) {
            float q = Qs[s * HID + h];
            sq += q;
#pragma unroll
            for (int i = 0; i < 2; i++) {
                float t  = a[i] + q;
                float t2 = t * t;
                float p  = fmaf(C2, t2, C1);
                float v  = t * p;
                float th = tanhf_hw(v);             // MUFU.TANH
                acc[i]   = fmaf(t, th, acc[i]);
            }
        }
    }

    // sum_s gelu = 0.5*(acc + S*a + sq)
    float sums[2];
#pragma unroll
    for (int i = 0; i < 2; i++)
        sums[i] = 0.5f * (acc[i] + fmaf((float)S_TOTAL, a[i], sq));

    // Epilogue
    __syncthreads();
    float* Gs = Qs;                        // overlay (8*64 floats)
#pragma unroll
    for (int i = 0; i < 2; i++)
        Gs[(group * 2 + i) * HID + h] = sums[i];
    __syncthreads();

    // 256 outputs = 8 j * 32 c, one per thread
    {
        int jj = tid >> 5;
        int c  = tid & 31;
        float sum = 0.0f;
#pragma unroll
        for (int hh = 0; hh < HID; hh++)
            sum = fmaf(Gs[jj * HID + hh], W2s[hh * C_OUT + c], sum);
        out[((size_t)b * C_OUT + c) * J_TOTAL + (j0 + jj)] =
            fmaf(sum, 1.0f / (float)S_TOTAL, b2s[c]);
    }
}

extern "C" void kernel_launch(void* const* d_in, const int* in_sizes, int n_in,
                              void* d_out, int out_size) {
    const float* v       = (const float*)d_in[0];
    const int*   indices = (const int*)d_in[1];
    const float* W1      = (const float*)d_in[2];
    const float* b1      = (const float*)d_in[3];
    const float* W2      = (const float*)d_in[4];
    const float* b2      = (const float*)d_in[5];
    float*       out     = (float*)d_out;

    precompute_q<<<dim3(S_TOTAL, B_TOTAL), HID>>>(v, indices, W1, b1);
    nystrom_main<<<dim3(J_TOTAL / JPB, B_TOTAL), 256>>>(W1, W2, b2, out);
}